// round 13
// baseline (speedup 1.0000x reference)
#include <cuda_runtime.h>
#include <cstdint>
#include <math.h>

#define BB 64
#define MM 8192
#define VV 128
#define FEPS 1e-8f
#define SEL_CAP 1024

// Scratch (device globals: no allocation allowed in kernel_launch)
__device__ float g_sim[BB * MM];   // 2 MB similarity per slot

// ---- order-preserving float<->uint key mapping (larger float => larger key) ----
__device__ __forceinline__ unsigned f2k(float f) {
    unsigned b = __float_as_uint(f);
    return (b & 0x80000000u) ? ~b : (b | 0x80000000u);
}
__device__ __forceinline__ float k2f(unsigned u) {
    unsigned b = (u & 0x80000000u) ? (u ^ 0x80000000u) : ~u;
    return __uint_as_float(b);
}

// ============================================================================
// Pass 1 (R6 proven, byte-identical): sim = dot(mem+eps, v+eps)/max(||.||*||.||, eps)
// 8 lanes/row, 4 rows/warp, 8 independent streaming LDG.128 per thread.
// 256 threads -> 64 rows/block. Grid: (MM/64, BB).
// Fires the PDL completion trigger after its stores.
// ============================================================================
__global__ void __launch_bounds__(256) sim_kernel(const float* __restrict__ mem,
                                                  const float* __restrict__ vin) {
    __shared__ __align__(16) float sv[VV];
    __shared__ float s_nb;
    const int b   = blockIdx.y;
    const int tid = threadIdx.x;

    if (tid < VV) sv[tid] = vin[b * VV + tid] + FEPS;
    __syncthreads();
    if (tid < 32) {
        float s = 0.f;
        #pragma unroll
        for (int i = tid; i < VV; i += 32) { float x = sv[i]; s += x * x; }
        #pragma unroll
        for (int o = 16; o; o >>= 1) s += __shfl_xor_sync(0xffffffffu, s, o);
        if (tid == 0) s_nb = sqrtf(s);
    }
    __syncthreads();

    const float nb   = s_nb;
    const int   warp = tid >> 5;
    const int   lane = tid & 31;
    const int   rw   = lane >> 3;   // row within warp's 4-row group
    const int   s    = lane & 7;    // float4 segment within row (0..7)

    const float4* svq = reinterpret_cast<const float4*>(sv);
    const float4 q0 = svq[s], q1 = svq[s + 8], q2 = svq[s + 16], q3 = svq[s + 24];

    const int m0 = blockIdx.x * 64 + warp * 4 + rw;
    const int m1 = m0 + 32;
    const float4* rowA = reinterpret_cast<const float4*>(mem + ((size_t)b * MM + m0) * VV);
    const float4* rowB = reinterpret_cast<const float4*>(mem + ((size_t)b * MM + m1) * VV);

    float4 a0 = __ldcs(rowA + s);      float4 a1 = __ldcs(rowA + s + 8);
    float4 a2 = __ldcs(rowA + s + 16); float4 a3 = __ldcs(rowA + s + 24);
    float4 b0 = __ldcs(rowB + s);      float4 b1 = __ldcs(rowB + s + 8);
    float4 b2 = __ldcs(rowB + s + 16); float4 b3 = __ldcs(rowB + s + 24);

    float numA = 0.f, ssA = 0.f, numB = 0.f, ssB = 0.f;
    #define ACC(X, Q, NUM, SS)                                        \
        { float e0 = X.x + FEPS, e1 = X.y + FEPS,                     \
                e2 = X.z + FEPS, e3 = X.w + FEPS;                     \
          NUM += e0 * Q.x + e1 * Q.y + e2 * Q.z + e3 * Q.w;           \
          SS  += e0 * e0 + e1 * e1 + e2 * e2 + e3 * e3; }
    ACC(a0, q0, numA, ssA) ACC(a1, q1, numA, ssA)
    ACC(a2, q2, numA, ssA) ACC(a3, q3, numA, ssA)
    ACC(b0, q0, numB, ssB) ACC(b1, q1, numB, ssB)
    ACC(b2, q2, numB, ssB) ACC(b3, q3, numB, ssB)
    #undef ACC

    #pragma unroll
    for (int o = 4; o; o >>= 1) {
        numA += __shfl_xor_sync(0xffffffffu, numA, o);
        ssA  += __shfl_xor_sync(0xffffffffu, ssA,  o);
        numB += __shfl_xor_sync(0xffffffffu, numB, o);
        ssB  += __shfl_xor_sync(0xffffffffu, ssB,  o);
    }
    if (s == 0) {
        g_sim[b * MM + m0] = numA / fmaxf(sqrtf(ssA) * nb, FEPS);
        g_sim[b * MM + m1] = numB / fmaxf(sqrtf(ssB) * nb, FEPS);
    }

    // PDL: this block's dependent-kernel-visible work is done
    cudaTriggerProgrammaticLaunchCompletion();
}

// ============================================================================
// Pass 2 (fused select + read) — EXACT R6 body (converged at ~9.6us), with a
// PDL grid-dependency sync: smem init happens while sim is still draining;
// key loads wait on the grid dependency. One block of 1024 threads per batch.
// ============================================================================
__global__ void __launch_bounds__(1024) select_read_kernel(
        const int* __restrict__ topk_ptr,
        const float* __restrict__ mem,
        const float* __restrict__ vin,
        float* __restrict__ out) {
    __shared__ int      hist[256];
    __shared__ int      wsum[8];
    __shared__ unsigned s_prefix;
    __shared__ int      s_k, s_cnt;
    __shared__ int      s_idx[SEL_CAP];
    __shared__ float    s_w[SEL_CAP];
    __shared__ float    s_part[8][VV];
    __shared__ float    s_sw2;

    const int b    = blockIdx.x;
    const int tid  = threadIdx.x;
    const int lane = tid & 31;

    // Pre-dependency work: runs while sim_kernel is still finishing
    if (tid == 0) { s_prefix = 0u; s_k = *topk_ptr; s_cnt = 0; }
    if (tid < 256) hist[tid] = 0;

    // Wait for sim_kernel's completion trigger, then load keys
    cudaGridDependencySynchronize();

    unsigned uk[8];
    #pragma unroll
    for (int j = 0; j < 8; j++)
        uk[j] = f2k(g_sim[b * MM + j * 1024 + tid]);
    __syncthreads();

    #pragma unroll
    for (int shift = 24; shift >= 0; shift -= 8) {
        const unsigned pmask  = (shift == 24) ? 0u : (0xFFFFFFFFu << (shift + 8));
        const unsigned prefix = s_prefix;
        #pragma unroll
        for (int j = 0; j < 8; j++) {
            unsigned u = uk[j];
            if ((u & pmask) == prefix)
                atomicAdd(&hist[(u >> shift) & 255], 1);
        }
        __syncthreads();
        // Parallel suffix-sum over bins (descending): thread t handles bin r=255-t.
        {
            const int r = 255 - tid;             // valid for tid < 256
            int v = (tid < 256) ? hist[r] : 0;
            #pragma unroll
            for (int o = 1; o < 32; o <<= 1) {
                int t = __shfl_up_sync(0xffffffffu, v, o);
                if (lane >= o) v += t;
            }
            if (tid < 256 && lane == 31) wsum[tid >> 5] = v;
            __syncthreads();
            if (tid < 256) {
                int add = 0;
                #pragma unroll
                for (int w = 0; w < 8; w++) add += (w < (tid >> 5)) ? wsum[w] : 0;
                int suf = v + add;               // inclusive suffix count at bin r
                int k   = s_k;
                int above = suf - hist[r];       // count in bins strictly above r
                if (suf >= k && above < k) {     // exactly one thread fires
                    s_k = k - above;
                    s_prefix = s_prefix | ((unsigned)r << shift);
                }
            }
        }
        __syncthreads();
        if (tid < 256) hist[tid] = 0;            // clear for next round
        __syncthreads();
    }

    const unsigned kthkey = s_prefix;
    #pragma unroll
    for (int j = 0; j < 8; j++) {
        unsigned u = uk[j];
        if (u >= kthkey) {
            int p = atomicAdd(&s_cnt, 1);
            if (p < SEL_CAP) { s_idx[p] = j * 1024 + tid; s_w[p] = k2f(u); }
        }
    }
    __syncthreads();

    int n = s_cnt; if (n > SEL_CAP) n = SEL_CAP;

    // sum of w^2 (one warp)
    if (tid < 32) {
        float sw2 = 0.f;
        for (int i = tid; i < n; i += 32) { float w = s_w[i]; sw2 += w * w; }
        #pragma unroll
        for (int o = 16; o; o >>= 1) sw2 += __shfl_xor_sync(0xffffffffu, sw2, o);
        if (tid == 0) s_sw2 = sw2;
    }

    // read: 8 groups of 128 threads accumulate over selected rows
    const int vcol = tid & (VV - 1);
    const int grp  = tid >> 7;
    float acc = 0.f;
    for (int i = grp; i < n; i += 8) {
        int   m = s_idx[i];
        float w = s_w[i];
        acc += w * mem[((size_t)b * MM + m) * VV + vcol];
    }
    s_part[grp][vcol] = acc;
    __syncthreads();

    if (tid < VV) {
        float a = 0.f;
        #pragma unroll
        for (int g = 0; g < 8; g++) a += s_part[g][tid];
        out[b * VV + tid] = a + s_sw2 * vin[b * VV + tid];
    }
}

// ============================================================================
extern "C" void kernel_launch(void* const* d_in, const int* in_sizes, int n_in,
                              void* d_out, int out_size) {
    const float* mem  = (const float*)d_in[0];   // (B, M, V) f32
    const float* vin  = (const float*)d_in[1];   // (B, V)    f32
    const int*   topk = (const int*)d_in[2];     // scalar    i32
    float*       out  = (float*)d_out;           // (B,1,1,V) f32

    sim_kernel<<<dim3(MM / 64, BB), 256>>>(mem, vin);

    // Dependent launch with PDL overlap: select_read's prologue runs while
    // sim_kernel drains; its key loads wait on the grid dependency.
    cudaLaunchConfig_t cfg = {};
    cfg.gridDim  = dim3(BB);
    cfg.blockDim = dim3(1024);
    cfg.dynamicSmemBytes = 0;
    cfg.stream   = 0;
    cudaLaunchAttribute attr[1];
    attr[0].id = cudaLaunchAttributeProgrammaticStreamSerialization;
    attr[0].val.programmaticStreamSerializationAllowed = 1;
    cfg.attrs    = attr;
    cfg.numAttrs = 1;
    cudaLaunchKernelEx(&cfg, select_read_kernel, topk, mem, vin, out);
}

// round 14
// speedup vs baseline: 1.0052x; 1.0052x over previous
#include <cuda_runtime.h>
#include <cstdint>
#include <math.h>

#define BB 64
#define MM 8192
#define VV 128
#define FEPS 1e-8f
#define SEL_CAP 1024

// Scratch (device globals: no allocation allowed in kernel_launch)
__device__ float g_sim[BB * MM];   // 2 MB similarity per slot

// ---- order-preserving float<->uint key mapping (larger float => larger key) ----
__device__ __forceinline__ unsigned f2k(float f) {
    unsigned b = __float_as_uint(f);
    return (b & 0x80000000u) ? ~b : (b | 0x80000000u);
}
__device__ __forceinline__ float k2f(unsigned u) {
    unsigned b = (u & 0x80000000u) ? (u ^ 0x80000000u) : ~u;
    return __uint_as_float(b);
}

// ============================================================================
// Pass 1 (R6 proven, byte-identical): sim = dot(mem+eps, v+eps)/max(||.||*||.||, eps)
// 8 lanes/row, 4 rows/warp, 8 independent streaming LDG.128 per thread.
// 256 threads -> 64 rows/block. Grid: (MM/64, BB). PDL trigger after stores.
// ============================================================================
__global__ void __launch_bounds__(256) sim_kernel(const float* __restrict__ mem,
                                                  const float* __restrict__ vin) {
    __shared__ __align__(16) float sv[VV];
    __shared__ float s_nb;
    const int b   = blockIdx.y;
    const int tid = threadIdx.x;

    if (tid < VV) sv[tid] = vin[b * VV + tid] + FEPS;
    __syncthreads();
    if (tid < 32) {
        float s = 0.f;
        #pragma unroll
        for (int i = tid; i < VV; i += 32) { float x = sv[i]; s += x * x; }
        #pragma unroll
        for (int o = 16; o; o >>= 1) s += __shfl_xor_sync(0xffffffffu, s, o);
        if (tid == 0) s_nb = sqrtf(s);
    }
    __syncthreads();

    const float nb   = s_nb;
    const int   warp = tid >> 5;
    const int   lane = tid & 31;
    const int   rw   = lane >> 3;   // row within warp's 4-row group
    const int   s    = lane & 7;    // float4 segment within row (0..7)

    const float4* svq = reinterpret_cast<const float4*>(sv);
    const float4 q0 = svq[s], q1 = svq[s + 8], q2 = svq[s + 16], q3 = svq[s + 24];

    const int m0 = blockIdx.x * 64 + warp * 4 + rw;
    const int m1 = m0 + 32;
    const float4* rowA = reinterpret_cast<const float4*>(mem + ((size_t)b * MM + m0) * VV);
    const float4* rowB = reinterpret_cast<const float4*>(mem + ((size_t)b * MM + m1) * VV);

    float4 a0 = __ldcs(rowA + s);      float4 a1 = __ldcs(rowA + s + 8);
    float4 a2 = __ldcs(rowA + s + 16); float4 a3 = __ldcs(rowA + s + 24);
    float4 b0 = __ldcs(rowB + s);      float4 b1 = __ldcs(rowB + s + 8);
    float4 b2 = __ldcs(rowB + s + 16); float4 b3 = __ldcs(rowB + s + 24);

    float numA = 0.f, ssA = 0.f, numB = 0.f, ssB = 0.f;
    #define ACC(X, Q, NUM, SS)                                        \
        { float e0 = X.x + FEPS, e1 = X.y + FEPS,                     \
                e2 = X.z + FEPS, e3 = X.w + FEPS;                     \
          NUM += e0 * Q.x + e1 * Q.y + e2 * Q.z + e3 * Q.w;           \
          SS  += e0 * e0 + e1 * e1 + e2 * e2 + e3 * e3; }
    ACC(a0, q0, numA, ssA) ACC(a1, q1, numA, ssA)
    ACC(a2, q2, numA, ssA) ACC(a3, q3, numA, ssA)
    ACC(b0, q0, numB, ssB) ACC(b1, q1, numB, ssB)
    ACC(b2, q2, numB, ssB) ACC(b3, q3, numB, ssB)
    #undef ACC

    #pragma unroll
    for (int o = 4; o; o >>= 1) {
        numA += __shfl_xor_sync(0xffffffffu, numA, o);
        ssA  += __shfl_xor_sync(0xffffffffu, ssA,  o);
        numB += __shfl_xor_sync(0xffffffffu, numB, o);
        ssB  += __shfl_xor_sync(0xffffffffu, ssB,  o);
    }
    if (s == 0) {
        g_sim[b * MM + m0] = numA / fmaxf(sqrtf(ssA) * nb, FEPS);
        g_sim[b * MM + m1] = numB / fmaxf(sqrtf(ssB) * nb, FEPS);
    }

    // PDL: this block's dependent-kernel-visible work is done
    cudaTriggerProgrammaticLaunchCompletion();
}

// ============================================================================
// Pass 2 — EXACT R6 body (converged 9.6us) with one insertion: the prologue
// (topk load, counters) runs BEFORE cudaGridDependencySynchronize(); key
// loads wait on the dependency. One block of 1024 threads per batch.
// ============================================================================
__global__ void __launch_bounds__(1024) select_read_kernel(
        const int* __restrict__ topk_ptr,
        const float* __restrict__ mem,
        const float* __restrict__ vin,
        float* __restrict__ out) {
    __shared__ int      hist[256];
    __shared__ int      wsum[8];
    __shared__ unsigned s_prefix;
    __shared__ int      s_k, s_cnt;
    __shared__ int      s_idx[SEL_CAP];
    __shared__ float    s_w[SEL_CAP];
    __shared__ float    s_part[8][VV];
    __shared__ float    s_sw2;

    const int b    = blockIdx.x;
    const int tid  = threadIdx.x;
    const int lane = tid & 31;

    // Pre-dependency prologue: runs while sim_kernel drains
    if (tid == 0) { s_prefix = 0u; s_k = *topk_ptr; s_cnt = 0; }

    // Wait for sim_kernel's completion trigger, then load keys
    cudaGridDependencySynchronize();

    unsigned uk[8];
    #pragma unroll
    for (int j = 0; j < 8; j++)
        uk[j] = f2k(g_sim[b * MM + j * 1024 + tid]);
    __syncthreads();

    #pragma unroll
    for (int shift = 24; shift >= 0; shift -= 8) {
        if (tid < 256) hist[tid] = 0;
        __syncthreads();
        const unsigned pmask  = (shift == 24) ? 0u : (0xFFFFFFFFu << (shift + 8));
        const unsigned prefix = s_prefix;
        #pragma unroll
        for (int j = 0; j < 8; j++) {
            unsigned u = uk[j];
            if ((u & pmask) == prefix)
                atomicAdd(&hist[(u >> shift) & 255], 1);
        }
        __syncthreads();
        // Parallel suffix-sum over bins (descending): thread t handles bin r=255-t.
        {
            const int r = 255 - tid;             // valid for tid < 256
            int v = (tid < 256) ? hist[r] : 0;
            #pragma unroll
            for (int o = 1; o < 32; o <<= 1) {
                int t = __shfl_up_sync(0xffffffffu, v, o);
                if (lane >= o) v += t;
            }
            if (tid < 256 && lane == 31) wsum[tid >> 5] = v;
            __syncthreads();
            if (tid < 256) {
                int add = 0;
                #pragma unroll
                for (int w = 0; w < 8; w++) add += (w < (tid >> 5)) ? wsum[w] : 0;
                int suf = v + add;               // inclusive suffix count at bin r
                int k   = s_k;
                int above = suf - hist[r];       // count in bins strictly above r
                if (suf >= k && above < k) {     // exactly one thread fires
                    s_k = k - above;
                    s_prefix = s_prefix | ((unsigned)r << shift);
                }
            }
        }
        __syncthreads();
    }

    const unsigned kthkey = s_prefix;
    #pragma unroll
    for (int j = 0; j < 8; j++) {
        unsigned u = uk[j];
        if (u >= kthkey) {
            int p = atomicAdd(&s_cnt, 1);
            if (p < SEL_CAP) { s_idx[p] = j * 1024 + tid; s_w[p] = k2f(u); }
        }
    }
    __syncthreads();

    int n = s_cnt; if (n > SEL_CAP) n = SEL_CAP;

    // sum of w^2 (one warp)
    if (tid < 32) {
        float sw2 = 0.f;
        for (int i = tid; i < n; i += 32) { float w = s_w[i]; sw2 += w * w; }
        #pragma unroll
        for (int o = 16; o; o >>= 1) sw2 += __shfl_xor_sync(0xffffffffu, sw2, o);
        if (tid == 0) s_sw2 = sw2;
    }

    // read: 8 groups of 128 threads accumulate over selected rows
    const int vcol = tid & (VV - 1);
    const int grp  = tid >> 7;
    float acc = 0.f;
    for (int i = grp; i < n; i += 8) {
        int   m = s_idx[i];
        float w = s_w[i];
        acc += w * mem[((size_t)b * MM + m) * VV + vcol];
    }
    s_part[grp][vcol] = acc;
    __syncthreads();

    if (tid < VV) {
        float a = 0.f;
        #pragma unroll
        for (int g = 0; g < 8; g++) a += s_part[g][tid];
        out[b * VV + tid] = a + s_sw2 * vin[b * VV + tid];
    }
}

// ============================================================================
extern "C" void kernel_launch(void* const* d_in, const int* in_sizes, int n_in,
                              void* d_out, int out_size) {
    const float* mem  = (const float*)d_in[0];   // (B, M, V) f32
    const float* vin  = (const float*)d_in[1];   // (B, V)    f32
    const int*   topk = (const int*)d_in[2];     // scalar    i32
    float*       out  = (float*)d_out;           // (B,1,1,V) f32

    sim_kernel<<<dim3(MM / 64, BB), 256>>>(mem, vin);

    // Dependent launch with PDL overlap
    cudaLaunchConfig_t cfg = {};
    cfg.gridDim  = dim3(BB);
    cfg.blockDim = dim3(1024);
    cfg.dynamicSmemBytes = 0;
    cfg.stream   = 0;
    cudaLaunchAttribute attr[1];
    attr[0].id = cudaLaunchAttributeProgrammaticStreamSerialization;
    attr[0].val.programmaticStreamSerializationAllowed = 1;
    cfg.attrs    = attr;
    cfg.numAttrs = 1;
    cudaLaunchKernelEx(&cfg, select_read_kernel, topk, mem, vin, out);
}